// round 4
// baseline (speedup 1.0000x reference)
#include <cuda_runtime.h>
#include <math.h>

// RNNLayer_73074573574765: delayed RNN. B=64,S=512,I=H=1024,DELAY=4.
// Phase 1: pre = X.Wih^T + bih + bhh  (FFMA2 GEMM, 128x128x8 tiles)
// Phase 2: ONE persistent kernel; 128 groups of 4 independent steps,
//          software grid barrier; last group also writes h_final.

namespace {
constexpr int Bz = 64;
constexpr int Sz = 512;
constexpr int Iz = 1024;
constexpr int Hz = 1024;
constexpr int DZ = 4;
constexpr int NBLK = 128;
constexpr int BM = 32;
constexpr int BN = 64;
constexpr int BK = 32;
constexpr int NGROUP = Sz / DZ;  // 128
}  // namespace

typedef unsigned long long u64;

__device__ float g_pre[(size_t)Bz * Sz * Hz];
__device__ unsigned g_cnt;  // zero-init; self-cleaning
__device__ unsigned g_gen;  // monotonic; equality-compared (replay-safe)

__device__ __forceinline__ u64 ffma2(u64 a, u64 b, u64 c) {
  u64 d;
  asm("fma.rn.f32x2 %0, %1, %2, %3;" : "=l"(d) : "l"(a), "l"(b), "l"(c));
  return d;
}
__device__ __forceinline__ u64 fadd2(u64 a, u64 b) {
  u64 d;
  asm("add.rn.f32x2 %0, %1, %2;" : "=l"(d) : "l"(a), "l"(b));
  return d;
}
__device__ __forceinline__ float2 unpack2(u64 v) {
  float2 f;
  asm("mov.b64 {%0, %1}, %2;" : "=f"(f.x), "=f"(f.y) : "l"(v));
  return f;
}

__device__ __forceinline__ void grid_barrier() {
  __syncthreads();
  if (threadIdx.x == 0) {
    unsigned gen = *(volatile unsigned*)&g_gen;
    __threadfence();
    if (atomicAdd(&g_cnt, 1) == NBLK - 1) {
      g_cnt = 0;
      __threadfence();
      atomicAdd(&g_gen, 1);
    } else {
      while (*(volatile unsigned*)&g_gen == gen) __nanosleep(32);
    }
    __threadfence();
  }
  __syncthreads();
}

// ---------------------------------------------------------------------------
// Phase 1: pre[m,n] = sum_k X[m,k]*Wih[n,k] + bih[n]+bhh[n]
// M=32768,N=1024,K=1024. BM=BN=128, BK=8, 256 thr, 8x8/thread via 32 FFMA2/k.
// A dup-stored ({a,a} pairs); B natural pairs. Double-buffered, reg-prefetch.
// ---------------------------------------------------------------------------
__global__ __launch_bounds__(256, 2) void pre_gemm_kernel(
    const float* __restrict__ X, const float* __restrict__ Wih,
    const float* __restrict__ bih, const float* __restrict__ bhh) {
  __shared__ __align__(16) float2 A1[2][8][128];  // dup pairs, 16 KB
  __shared__ __align__(16) float2 B1[2][8][64];   // natural pairs, 8 KB

  const int tid = threadIdx.x;
  const int bm = blockIdx.y;
  const int bn = blockIdx.x;

  // loaders: 256 threads cover 128 rows x 8 k (one float4 each)
  const int lrow = tid >> 1;
  const int lcol = (tid & 1) << 2;
  const float* Ag = X + (size_t)(bm * 128 + lrow) * Iz + lcol;
  const float* Bg = Wih + (size_t)(bn * 128 + lrow) * Iz + lcol;

  const int tr = tid >> 4;  // rows tr*8..+7
  const int tc = tid & 15;  // cols tc*8..+7

  u64 acc[8][4];
#pragma unroll
  for (int i = 0; i < 8; i++)
#pragma unroll
    for (int j = 0; j < 4; j++) acc[i][j] = 0ull;

  float4 pa = *reinterpret_cast<const float4*>(Ag);
  float4 pb = *reinterpret_cast<const float4*>(Bg);
  {
    float av[4] = {pa.x, pa.y, pa.z, pa.w};
    float bv[4] = {pb.x, pb.y, pb.z, pb.w};
#pragma unroll
    for (int i = 0; i < 4; i++) {
      A1[0][lcol + i][lrow] = make_float2(av[i], av[i]);
      reinterpret_cast<float*>(&B1[0][lcol + i][0])[lrow] = bv[i];
    }
  }
  __syncthreads();

  const int NIT = Iz / 8;  // 128
  for (int it = 0; it < NIT; ++it) {
    const int cur = it & 1;
    if (it + 1 < NIT) {
      pa = *reinterpret_cast<const float4*>(Ag + (it + 1) * 8);
      pb = *reinterpret_cast<const float4*>(Bg + (it + 1) * 8);
    }
#pragma unroll
    for (int k = 0; k < 8; k++) {
      const ulonglong2* ap =
          reinterpret_cast<const ulonglong2*>(&A1[cur][k][tr * 8]);
      const ulonglong2* bp =
          reinterpret_cast<const ulonglong2*>(&B1[cur][k][tc * 4]);
      u64 a[8], b[4];
#pragma unroll
      for (int i = 0; i < 4; i++) {
        ulonglong2 v = ap[i];
        a[2 * i] = v.x;
        a[2 * i + 1] = v.y;
      }
#pragma unroll
      for (int j = 0; j < 2; j++) {
        ulonglong2 v = bp[j];
        b[2 * j] = v.x;
        b[2 * j + 1] = v.y;
      }
#pragma unroll
      for (int i = 0; i < 8; i++)
#pragma unroll
        for (int j = 0; j < 4; j++) acc[i][j] = ffma2(a[i], b[j], acc[i][j]);
    }
    if (it + 1 < NIT) {
      const int nxt = cur ^ 1;
      float av[4] = {pa.x, pa.y, pa.z, pa.w};
      float bv[4] = {pb.x, pb.y, pb.z, pb.w};
#pragma unroll
      for (int i = 0; i < 4; i++) {
        A1[nxt][lcol + i][lrow] = make_float2(av[i], av[i]);
        reinterpret_cast<float*>(&B1[nxt][lcol + i][0])[lrow] = bv[i];
      }
    }
    __syncthreads();
  }

  float bias[8];
#pragma unroll
  for (int j = 0; j < 8; j++) {
    int n = bn * 128 + tc * 8 + j;
    bias[j] = bih[n] + bhh[n];
  }

#pragma unroll
  for (int i = 0; i < 8; i++) {
    size_t row = (size_t)(bm * 128 + tr * 8 + i) * Hz;
    size_t col = (size_t)bn * 128 + tc * 8;
#pragma unroll
    for (int jp = 0; jp < 4; jp += 2) {
      float2 v0 = unpack2(acc[i][jp]);
      float2 v1 = unpack2(acc[i][jp + 1]);
      float4 v;
      v.x = v0.x + bias[jp * 2 + 0];
      v.y = v0.y + bias[jp * 2 + 1];
      v.z = v1.x + bias[jp * 2 + 2];
      v.w = v1.y + bias[jp * 2 + 3];
      *reinterpret_cast<float4*>(&g_pre[row + col + jp * 2]) = v;
    }
  }
}

// ---------------------------------------------------------------------------
// Phase 2 persistent kernel. Block tile 32x64, 512 thr, thread tile 2x2,
// split even/odd-k accumulator chains. Last group also writes h_final.
// ---------------------------------------------------------------------------
__global__ __launch_bounds__(512, 1) void rnn_persistent(
    const float* __restrict__ hs, const float* __restrict__ Whh,
    float* __restrict__ out, float* __restrict__ hf) {
  __shared__ __align__(16) float2 Ad[2][BK][BM + 2];
  __shared__ float2 Bp[2][BK][BN / 2 + 1];

  const int tid = threadIdx.x;
  const int bmi = blockIdx.x >> 4;  // 0..7
  const int bni = blockIdx.x & 15;  // 0..15

  // A loader: row am (0..31), k-pair akq (0..15)
  const int am = tid >> 4;
  const int akq = tid & 15;
  const int m_abs_l = bmi * BM + am;
  const int dl = m_abs_l >> 6;
  const int bl = m_abs_l & 63;
  // B loader: row bn (0..63), k-quad bkq (0..7)
  const int bn = tid >> 3;
  const int bkq = tid & 7;
  const float* wrow = Whh + (size_t)(bni * BN + bn) * Hz + 4 * bkq;

  const int w = tid >> 5;
  const int lane = tid & 31;
  const int wm = w >> 2, wn = w & 3;
  const int pm = wm * 4 + (lane >> 3);
  const int pn = wn * 8 + (lane & 7);

  for (int g = 0; g < NGROUP; ++g) {
    const float* hrow =
        (g == 0)
            ? hs + (size_t)m_abs_l * Hz + 2 * akq
            : out + ((size_t)bl * Sz + (4 * g + dl - 4)) * Hz + 2 * akq;

    u64 acc0a = 0ull, acc0b = 0ull, acc1a = 0ull, acc1b = 0ull;

    float2 pa = *reinterpret_cast<const float2*>(hrow);
    float4 pb = *reinterpret_cast<const float4*>(wrow);
    Ad[0][2 * akq + 0][am] = make_float2(pa.x, pa.x);
    Ad[0][2 * akq + 1][am] = make_float2(pa.y, pa.y);
    reinterpret_cast<float*>(&Bp[0][4 * bkq + 0][0])[bn] = pb.x;
    reinterpret_cast<float*>(&Bp[0][4 * bkq + 1][0])[bn] = pb.y;
    reinterpret_cast<float*>(&Bp[0][4 * bkq + 2][0])[bn] = pb.z;
    reinterpret_cast<float*>(&Bp[0][4 * bkq + 3][0])[bn] = pb.w;
    __syncthreads();

    const int NC = Hz / BK;  // 32
    for (int c = 0; c < NC; ++c) {
      const int cur = c & 1;
      if (c + 1 < NC) {
        pa = *reinterpret_cast<const float2*>(hrow + (c + 1) * BK);
        pb = *reinterpret_cast<const float4*>(wrow + (c + 1) * BK);
      }
#pragma unroll
      for (int k = 0; k < BK; k += 2) {
        ulonglong2 av0 =
            *reinterpret_cast<const ulonglong2*>(&Ad[cur][k][2 * pm]);
        u64 bv0 = *reinterpret_cast<const u64*>(&Bp[cur][k][pn]);
        acc0a = ffma2(av0.x, bv0, acc0a);
        acc1a = ffma2(av0.y, bv0, acc1a);
        ulonglong2 av1 =
            *reinterpret_cast<const ulonglong2*>(&Ad[cur][k + 1][2 * pm]);
        u64 bv1 = *reinterpret_cast<const u64*>(&Bp[cur][k + 1][pn]);
        acc0b = ffma2(av1.x, bv1, acc0b);
        acc1b = ffma2(av1.y, bv1, acc1b);
      }
      if (c + 1 < NC) {
        const int nxt = cur ^ 1;
        Ad[nxt][2 * akq + 0][am] = make_float2(pa.x, pa.x);
        Ad[nxt][2 * akq + 1][am] = make_float2(pa.y, pa.y);
        reinterpret_cast<float*>(&Bp[nxt][4 * bkq + 0][0])[bn] = pb.x;
        reinterpret_cast<float*>(&Bp[nxt][4 * bkq + 1][0])[bn] = pb.y;
        reinterpret_cast<float*>(&Bp[nxt][4 * bkq + 2][0])[bn] = pb.z;
        reinterpret_cast<float*>(&Bp[nxt][4 * bkq + 3][0])[bn] = pb.w;
      }
      __syncthreads();
    }

    u64 acc0 = fadd2(acc0a, acc0b);
    u64 acc1 = fadd2(acc1a, acc1b);

    {
      const int n_off = bni * BN + 2 * pn;
#pragma unroll
      for (int i = 0; i < 2; ++i) {
        const int m_abs = bmi * BM + 2 * pm + i;
        const int d = m_abs >> 6;
        const int b = m_abs & 63;
        const size_t base = ((size_t)b * Sz + (4 * g + d)) * Hz + n_off;
        float2 pv = *reinterpret_cast<const float2*>(&g_pre[base]);
        float2 ac = unpack2(i == 0 ? acc0 : acc1);
        float2 ov = make_float2(tanhf(pv.x + ac.x), tanhf(pv.y + ac.y));
        *reinterpret_cast<float2*>(&out[base]) = ov;
        if (g == NGROUP - 1) {
          *reinterpret_cast<float2*>(
              &hf[((size_t)d * Bz + b) * Hz + n_off]) = ov;
        }
      }
    }
    grid_barrier();
  }
}

extern "C" void kernel_launch(void* const* d_in, const int* in_sizes, int n_in,
                              void* d_out, int out_size) {
  (void)in_sizes;
  (void)n_in;
  (void)out_size;
  const float* X = (const float*)d_in[0];    // [B,S,I]
  const float* hs = (const float*)d_in[1];   // [4,B,H]
  const float* Wih = (const float*)d_in[2];  // [H,I]
  const float* Whh = (const float*)d_in[3];  // [H,H]
  const float* bih = (const float*)d_in[4];  // [H]
  const float* bhh = (const float*)d_in[5];  // [H]

  float* out = (float*)d_out;              // [B,S,H]
  float* hf = out + (size_t)Bz * Sz * Hz;  // [4,B,H]

  pre_gemm_kernel<<<dim3(Hz / 128, (Bz * Sz) / 128), 256>>>(X, Wih, bih, bhh);

  rnn_persistent<<<NBLK, 512>>>(hs, Whh, out, hf);
}

// round 8
// speedup vs baseline: 1.1402x; 1.1402x over previous
#include <cuda_runtime.h>
#include <math.h>
#include <cstdint>

// RNNLayer_73074573574765: delayed RNN. B=64,S=512,I=H=1024,DELAY=4.
// Phase 1: pre = X.Wih^T + bih + bhh  -- mma.sync tf32 3-pass split (fp32 acc)
//          (base-target PTX; tcgen05 is rejected by this harness's .target sm_103)
// Phase 2: R3-proven persistent FFMA2 kernel (128 groups, grid barrier)
// Phase 3: h_final copy.

namespace {
constexpr int Bz = 64;
constexpr int Sz = 512;
constexpr int Iz = 1024;
constexpr int Hz = 1024;
constexpr int DZ = 4;
constexpr int NBLK = 128;
constexpr int BM = 32;
constexpr int BN = 64;
constexpr int BK = 32;
constexpr int NGROUP = Sz / DZ;  // 128
}  // namespace

typedef unsigned long long u64;

__device__ float g_pre[(size_t)Bz * Sz * Hz];
__device__ unsigned g_cnt;  // zero-init; self-cleaning
__device__ unsigned g_gen;  // monotonic; equality-compared (replay-safe)

// ---------------- PTX helpers (all base-target legal) ----------------
__device__ __forceinline__ u64 ffma2(u64 a, u64 b, u64 c) {
  u64 d;
  asm("fma.rn.f32x2 %0, %1, %2, %3;" : "=l"(d) : "l"(a), "l"(b), "l"(c));
  return d;
}
__device__ __forceinline__ float2 unpack2(u64 v) {
  float2 f;
  asm("mov.b64 {%0, %1}, %2;" : "=f"(f.x), "=f"(f.y) : "l"(v));
  return f;
}
__device__ __forceinline__ uint32_t cvt_tf32(float f) {
  uint32_t r;
  asm("cvt.rna.tf32.f32 %0, %1;" : "=r"(r) : "f"(f));
  return r;
}
// D(16x8,f32) += A(16x8,tf32,row) * B(8x8,tf32,col)
__device__ __forceinline__ void mma_tf32(float* c, uint32_t a0, uint32_t a1,
                                         uint32_t a2, uint32_t a3, uint32_t b0,
                                         uint32_t b1) {
  asm volatile(
      "mma.sync.aligned.m16n8k8.row.col.f32.tf32.tf32.f32 "
      "{%0,%1,%2,%3}, {%4,%5,%6,%7}, {%8,%9}, {%0,%1,%2,%3};"
      : "+f"(c[0]), "+f"(c[1]), "+f"(c[2]), "+f"(c[3])
      : "r"(a0), "r"(a1), "r"(a2), "r"(a3), "r"(b0), "r"(b1));
}

// split one float into tf32 hi + tf32 lo bit-patterns
__device__ __forceinline__ void split_tf32(float x, uint32_t& hi,
                                           uint32_t& lo) {
  hi = cvt_tf32(x);
  lo = cvt_tf32(x - __uint_as_float(hi));
}

// ---------------------------------------------------------------------------
// Phase 1: pre[m,n] = sum_k X[m,k]*Wih[n,k] + bih[n]+bhh[n]
// M=32768 N=1024 K=1024. Block tile 128x128, BK=16, 256 thr (8 warps 2x4),
// warp tile 64x32 (4 mtiles x 4 ntiles of m16n8k8). 3xTF32 split.
// SMEM pitch 20 floats -> frag LDS (bank = 20*gid + tig) conflict-free.
// ---------------------------------------------------------------------------
__global__ __launch_bounds__(256) void pre_gemm_mma(
    const float* __restrict__ X, const float* __restrict__ Wih,
    const float* __restrict__ bih, const float* __restrict__ bhh) {
  __shared__ uint32_t Ah[128][20];
  __shared__ uint32_t Al[128][20];
  __shared__ uint32_t Bh[128][20];
  __shared__ uint32_t Bl[128][20];

  const int tid = threadIdx.x;
  const int bn = blockIdx.x;  // 0..7
  const int bm = blockIdx.y;  // 0..255
  const int w = tid >> 5;
  const int lane = tid & 31;
  const int gid = lane >> 2;  // 0..7
  const int tig = lane & 3;   // 0..3
  const int wm = w >> 2;      // 0..1
  const int wn = w & 3;       // 0..3

  // loader: 512 float4 per matrix per chunk; thread covers rows r0,r1 quad q
  const int r0 = tid >> 2;        // 0..63
  const int r1 = r0 + 64;         // 64..127
  const int q = tid & 3;          // 0..3 (k-quad)
  const float* Abase = X + (size_t)(bm * 128) * Iz;
  const float* Bbase = Wih + (size_t)(bn * 128) * Iz;

  float c[4][4][4];
#pragma unroll
  for (int i = 0; i < 4; i++)
#pragma unroll
    for (int j = 0; j < 4; j++)
#pragma unroll
      for (int e = 0; e < 4; e++) c[i][j][e] = 0.f;

  float4 pa0, pa1, pb0, pb1;
  pa0 = *reinterpret_cast<const float4*>(Abase + (size_t)r0 * Iz + q * 4);
  pa1 = *reinterpret_cast<const float4*>(Abase + (size_t)r1 * Iz + q * 4);
  pb0 = *reinterpret_cast<const float4*>(Bbase + (size_t)r0 * Iz + q * 4);
  pb1 = *reinterpret_cast<const float4*>(Bbase + (size_t)r1 * Iz + q * 4);

  const int NCH = Iz / 16;  // 64
  for (int ch = 0; ch < NCH; ++ch) {
    // stage hi/lo into SMEM
    {
      uint4 h, l;
      split_tf32(pa0.x, h.x, l.x); split_tf32(pa0.y, h.y, l.y);
      split_tf32(pa0.z, h.z, l.z); split_tf32(pa0.w, h.w, l.w);
      *reinterpret_cast<uint4*>(&Ah[r0][q * 4]) = h;
      *reinterpret_cast<uint4*>(&Al[r0][q * 4]) = l;
      split_tf32(pa1.x, h.x, l.x); split_tf32(pa1.y, h.y, l.y);
      split_tf32(pa1.z, h.z, l.z); split_tf32(pa1.w, h.w, l.w);
      *reinterpret_cast<uint4*>(&Ah[r1][q * 4]) = h;
      *reinterpret_cast<uint4*>(&Al[r1][q * 4]) = l;
      split_tf32(pb0.x, h.x, l.x); split_tf32(pb0.y, h.y, l.y);
      split_tf32(pb0.z, h.z, l.z); split_tf32(pb0.w, h.w, l.w);
      *reinterpret_cast<uint4*>(&Bh[r0][q * 4]) = h;
      *reinterpret_cast<uint4*>(&Bl[r0][q * 4]) = l;
      split_tf32(pb1.x, h.x, l.x); split_tf32(pb1.y, h.y, l.y);
      split_tf32(pb1.z, h.z, l.z); split_tf32(pb1.w, h.w, l.w);
      *reinterpret_cast<uint4*>(&Bh[r1][q * 4]) = h;
      *reinterpret_cast<uint4*>(&Bl[r1][q * 4]) = l;
    }
    __syncthreads();

    if (ch + 1 < NCH) {  // prefetch next chunk (latency under compute)
      const size_t ko = (size_t)(ch + 1) * 16 + q * 4;
      pa0 = *reinterpret_cast<const float4*>(Abase + (size_t)r0 * Iz + ko);
      pa1 = *reinterpret_cast<const float4*>(Abase + (size_t)r1 * Iz + ko);
      pb0 = *reinterpret_cast<const float4*>(Bbase + (size_t)r0 * Iz + ko);
      pb1 = *reinterpret_cast<const float4*>(Bbase + (size_t)r1 * Iz + ko);
    }

#pragma unroll
    for (int ks = 0; ks < 2; ++ks) {
      const int k0 = ks * 8;
      uint32_t ah[4][4], al[4][4];
#pragma unroll
      for (int mt = 0; mt < 4; ++mt) {
        const int ra = wm * 64 + mt * 16 + gid;
        ah[mt][0] = Ah[ra][k0 + tig];
        ah[mt][1] = Ah[ra + 8][k0 + tig];
        ah[mt][2] = Ah[ra][k0 + tig + 4];
        ah[mt][3] = Ah[ra + 8][k0 + tig + 4];
        al[mt][0] = Al[ra][k0 + tig];
        al[mt][1] = Al[ra + 8][k0 + tig];
        al[mt][2] = Al[ra][k0 + tig + 4];
        al[mt][3] = Al[ra + 8][k0 + tig + 4];
      }
      uint32_t bh[4][2], bl[4][2];
#pragma unroll
      for (int nt = 0; nt < 4; ++nt) {
        const int rb = wn * 32 + nt * 8 + gid;
        bh[nt][0] = Bh[rb][k0 + tig];
        bh[nt][1] = Bh[rb][k0 + tig + 4];
        bl[nt][0] = Bl[rb][k0 + tig];
        bl[nt][1] = Bl[rb][k0 + tig + 4];
      }
#pragma unroll
      for (int mt = 0; mt < 4; ++mt)
#pragma unroll
        for (int nt = 0; nt < 4; ++nt) {
          mma_tf32(c[mt][nt], ah[mt][0], ah[mt][1], ah[mt][2], ah[mt][3],
                   bl[nt][0], bl[nt][1]);
          mma_tf32(c[mt][nt], al[mt][0], al[mt][1], al[mt][2], al[mt][3],
                   bh[nt][0], bh[nt][1]);
          mma_tf32(c[mt][nt], ah[mt][0], ah[mt][1], ah[mt][2], ah[mt][3],
                   bh[nt][0], bh[nt][1]);
        }
    }
    __syncthreads();
  }

  // epilogue: bias + store (float2 per c-pair)
#pragma unroll
  for (int nt = 0; nt < 4; ++nt) {
    const int n = bn * 128 + wn * 32 + nt * 8 + 2 * tig;
    const float bx = bih[n] + bhh[n];
    const float by = bih[n + 1] + bhh[n + 1];
#pragma unroll
    for (int mt = 0; mt < 4; ++mt) {
      const int m = bm * 128 + wm * 64 + mt * 16 + gid;
      float2 v0 = make_float2(c[mt][nt][0] + bx, c[mt][nt][1] + by);
      float2 v1 = make_float2(c[mt][nt][2] + bx, c[mt][nt][3] + by);
      *reinterpret_cast<float2*>(&g_pre[(size_t)m * Hz + n]) = v0;
      *reinterpret_cast<float2*>(&g_pre[(size_t)(m + 8) * Hz + n]) = v1;
    }
  }
}

// ---------------------------------------------------------------------------
// grid barrier (R3-proven)
// ---------------------------------------------------------------------------
__device__ __forceinline__ void grid_barrier() {
  __syncthreads();
  if (threadIdx.x == 0) {
    unsigned gen = *(volatile unsigned*)&g_gen;
    __threadfence();
    if (atomicAdd(&g_cnt, 1) == NBLK - 1) {
      g_cnt = 0;
      __threadfence();
      atomicAdd(&g_gen, 1);
    } else {
      while (*(volatile unsigned*)&g_gen == gen) __nanosleep(32);
    }
    __threadfence();
  }
  __syncthreads();
}

// ---------------------------------------------------------------------------
// Phase 2 persistent kernel (R3 exact, measured best).
// ---------------------------------------------------------------------------
__global__ __launch_bounds__(512, 1) void rnn_persistent(
    const float* __restrict__ hs, const float* __restrict__ Whh,
    float* __restrict__ out) {
  __shared__ __align__(16) float2 Ad[2][BK][BM + 2];
  __shared__ float2 Bp[2][BK][BN / 2 + 1];

  const int tid = threadIdx.x;
  const int bmi = blockIdx.x >> 4;
  const int bni = blockIdx.x & 15;

  const int am = tid >> 4;
  const int akq = tid & 15;
  const int m_abs_l = bmi * BM + am;
  const int dl = m_abs_l >> 6;
  const int bl = m_abs_l & 63;
  const int bn = tid >> 3;
  const int bkq = tid & 7;
  const float* wrow = Whh + (size_t)(bni * BN + bn) * Hz + 4 * bkq;

  const int w = tid >> 5;
  const int lane = tid & 31;
  const int wm = w >> 2, wn = w & 3;
  const int pm = wm * 4 + (lane >> 3);
  const int pn = wn * 8 + (lane & 7);

  for (int g = 0; g < NGROUP; ++g) {
    const float* hrow =
        (g == 0)
            ? hs + (size_t)m_abs_l * Hz + 2 * akq
            : out + ((size_t)bl * Sz + (4 * g + dl - 4)) * Hz + 2 * akq;

    u64 acc0 = 0ull, acc1 = 0ull;

    float2 pa = *reinterpret_cast<const float2*>(hrow);
    float4 pb = *reinterpret_cast<const float4*>(wrow);
    Ad[0][2 * akq + 0][am] = make_float2(pa.x, pa.x);
    Ad[0][2 * akq + 1][am] = make_float2(pa.y, pa.y);
    reinterpret_cast<float*>(&Bp[0][4 * bkq + 0][0])[bn] = pb.x;
    reinterpret_cast<float*>(&Bp[0][4 * bkq + 1][0])[bn] = pb.y;
    reinterpret_cast<float*>(&Bp[0][4 * bkq + 2][0])[bn] = pb.z;
    reinterpret_cast<float*>(&Bp[0][4 * bkq + 3][0])[bn] = pb.w;
    __syncthreads();

    const int NC = Hz / BK;
    for (int c = 0; c < NC; ++c) {
      const int cur = c & 1;
      if (c + 1 < NC) {
        pa = *reinterpret_cast<const float2*>(hrow + (c + 1) * BK);
        pb = *reinterpret_cast<const float4*>(wrow + (c + 1) * BK);
      }
#pragma unroll
      for (int k = 0; k < BK; ++k) {
        ulonglong2 av =
            *reinterpret_cast<const ulonglong2*>(&Ad[cur][k][2 * pm]);
        u64 bv = *reinterpret_cast<const u64*>(&Bp[cur][k][pn]);
        acc0 = ffma2(av.x, bv, acc0);
        acc1 = ffma2(av.y, bv, acc1);
      }
      if (c + 1 < NC) {
        const int nxt = cur ^ 1;
        Ad[nxt][2 * akq + 0][am] = make_float2(pa.x, pa.x);
        Ad[nxt][2 * akq + 1][am] = make_float2(pa.y, pa.y);
        reinterpret_cast<float*>(&Bp[nxt][4 * bkq + 0][0])[bn] = pb.x;
        reinterpret_cast<float*>(&Bp[nxt][4 * bkq + 1][0])[bn] = pb.y;
        reinterpret_cast<float*>(&Bp[nxt][4 * bkq + 2][0])[bn] = pb.z;
        reinterpret_cast<float*>(&Bp[nxt][4 * bkq + 3][0])[bn] = pb.w;
      }
      __syncthreads();
    }

    {
      const int n_off = bni * BN + 2 * pn;
#pragma unroll
      for (int i = 0; i < 2; ++i) {
        const int m_abs = bmi * BM + 2 * pm + i;
        const int d = m_abs >> 6;
        const int b = m_abs & 63;
        const size_t base = ((size_t)b * Sz + (4 * g + d)) * Hz + n_off;
        float2 pv = *reinterpret_cast<const float2*>(&g_pre[base]);
        float2 ac = unpack2(i == 0 ? acc0 : acc1);
        float2 ov = make_float2(tanhf(pv.x + ac.x), tanhf(pv.y + ac.y));
        *reinterpret_cast<float2*>(&out[base]) = ov;
      }
    }
    grid_barrier();
  }
}

// ---------------------------------------------------------------------------
// Phase 3: h_final[d,b,h] = out[b, S-4+d, h]
// ---------------------------------------------------------------------------
__global__ void final_state_kernel(const float* __restrict__ out,
                                   float* __restrict__ hf) {
  int idx = blockIdx.x * 256 + threadIdx.x;
  int h = idx & (Hz - 1);
  int bd = idx >> 10;
  int b = bd & (Bz - 1);
  int d = bd >> 6;
  hf[idx] = out[((size_t)b * Sz + (Sz - DZ + d)) * Hz + h];
}

extern "C" void kernel_launch(void* const* d_in, const int* in_sizes, int n_in,
                              void* d_out, int out_size) {
  (void)in_sizes;
  (void)n_in;
  (void)out_size;
  const float* X = (const float*)d_in[0];    // [B,S,I]
  const float* hs = (const float*)d_in[1];   // [4,B,H]
  const float* Wih = (const float*)d_in[2];  // [H,I]
  const float* Whh = (const float*)d_in[3];  // [H,H]
  const float* bih = (const float*)d_in[4];  // [H]
  const float* bhh = (const float*)d_in[5];  // [H]

  float* out = (float*)d_out;              // [B,S,H]
  float* hf = out + (size_t)Bz * Sz * Hz;  // [4,B,H]

  pre_gemm_mma<<<dim3(Hz / 128, (Bz * Sz) / 128), 256>>>(X, Wih, bih, bhh);

  rnn_persistent<<<NBLK, 512>>>(hs, Whh, out);

  final_state_kernel<<<(DZ * Bz * Hz) / 256, 256>>>(out, hf);
}

// round 10
// speedup vs baseline: 1.6669x; 1.4619x over previous
#include <cuda_runtime.h>
#include <math.h>
#include <cstdint>

// RNNLayer_73074573574765: delayed RNN. B=64,S=512,I=H=1024,DELAY=4.
// Phase 1: pre = X.Wih^T + bih + bhh  -- mma.sync tf32 3-pass split (R8 proven)
// Phase 2: persistent mma.sync tf32 3-pass kernel; 128 groups, grid barrier;
//          last group also writes h_final.

namespace {
constexpr int Bz = 64;
constexpr int Sz = 512;
constexpr int Iz = 1024;
constexpr int Hz = 1024;
constexpr int DZ = 4;
constexpr int NBLK = 128;
constexpr int NGROUP = Sz / DZ;  // 128
}  // namespace

typedef unsigned long long u64;

__device__ float g_pre[(size_t)Bz * Sz * Hz];
__device__ unsigned g_cnt;  // zero-init; self-cleaning
__device__ unsigned g_gen;  // monotonic; equality-compared (replay-safe)

// ---------------- PTX helpers (base-target legal) ----------------
__device__ __forceinline__ uint32_t cvt_tf32(float f) {
  uint32_t r;
  asm("cvt.rna.tf32.f32 %0, %1;" : "=r"(r) : "f"(f));
  return r;
}
// D(16x8,f32) += A(16x8,tf32,row) * B(8x8,tf32,col)
__device__ __forceinline__ void mma_tf32(float* c, uint32_t a0, uint32_t a1,
                                         uint32_t a2, uint32_t a3, uint32_t b0,
                                         uint32_t b1) {
  asm volatile(
      "mma.sync.aligned.m16n8k8.row.col.f32.tf32.tf32.f32 "
      "{%0,%1,%2,%3}, {%4,%5,%6,%7}, {%8,%9}, {%0,%1,%2,%3};"
      : "+f"(c[0]), "+f"(c[1]), "+f"(c[2]), "+f"(c[3])
      : "r"(a0), "r"(a1), "r"(a2), "r"(a3), "r"(b0), "r"(b1));
}
__device__ __forceinline__ void split_tf32(float x, uint32_t& hi,
                                           uint32_t& lo) {
  hi = cvt_tf32(x);
  lo = cvt_tf32(x - __uint_as_float(hi));
}
__device__ __forceinline__ void split4(float4 v, uint4& h, uint4& l) {
  split_tf32(v.x, h.x, l.x);
  split_tf32(v.y, h.y, l.y);
  split_tf32(v.z, h.z, l.z);
  split_tf32(v.w, h.w, l.w);
}

// ---------------------------------------------------------------------------
// Phase 1 (R8 exact): pre[m,n] = sum_k X[m,k]*Wih[n,k] + bih[n]+bhh[n]
// ---------------------------------------------------------------------------
__global__ __launch_bounds__(256) void pre_gemm_mma(
    const float* __restrict__ X, const float* __restrict__ Wih,
    const float* __restrict__ bih, const float* __restrict__ bhh) {
  __shared__ uint32_t Ah[128][20];
  __shared__ uint32_t Al[128][20];
  __shared__ uint32_t Bh[128][20];
  __shared__ uint32_t Bl[128][20];

  const int tid = threadIdx.x;
  const int bn = blockIdx.x;
  const int bm = blockIdx.y;
  const int w = tid >> 5;
  const int lane = tid & 31;
  const int gid = lane >> 2;
  const int tig = lane & 3;
  const int wm = w >> 2;
  const int wn = w & 3;

  const int r0 = tid >> 2;
  const int r1 = r0 + 64;
  const int q = tid & 3;
  const float* Abase = X + (size_t)(bm * 128) * Iz;
  const float* Bbase = Wih + (size_t)(bn * 128) * Iz;

  float c[4][4][4];
#pragma unroll
  for (int i = 0; i < 4; i++)
#pragma unroll
    for (int j = 0; j < 4; j++)
#pragma unroll
      for (int e = 0; e < 4; e++) c[i][j][e] = 0.f;

  float4 pa0, pa1, pb0, pb1;
  pa0 = *reinterpret_cast<const float4*>(Abase + (size_t)r0 * Iz + q * 4);
  pa1 = *reinterpret_cast<const float4*>(Abase + (size_t)r1 * Iz + q * 4);
  pb0 = *reinterpret_cast<const float4*>(Bbase + (size_t)r0 * Iz + q * 4);
  pb1 = *reinterpret_cast<const float4*>(Bbase + (size_t)r1 * Iz + q * 4);

  const int NCH = Iz / 16;  // 64
  for (int ch = 0; ch < NCH; ++ch) {
    {
      uint4 h, l;
      split4(pa0, h, l);
      *reinterpret_cast<uint4*>(&Ah[r0][q * 4]) = h;
      *reinterpret_cast<uint4*>(&Al[r0][q * 4]) = l;
      split4(pa1, h, l);
      *reinterpret_cast<uint4*>(&Ah[r1][q * 4]) = h;
      *reinterpret_cast<uint4*>(&Al[r1][q * 4]) = l;
      split4(pb0, h, l);
      *reinterpret_cast<uint4*>(&Bh[r0][q * 4]) = h;
      *reinterpret_cast<uint4*>(&Bl[r0][q * 4]) = l;
      split4(pb1, h, l);
      *reinterpret_cast<uint4*>(&Bh[r1][q * 4]) = h;
      *reinterpret_cast<uint4*>(&Bl[r1][q * 4]) = l;
    }
    __syncthreads();

    if (ch + 1 < NCH) {
      const size_t ko = (size_t)(ch + 1) * 16 + q * 4;
      pa0 = *reinterpret_cast<const float4*>(Abase + (size_t)r0 * Iz + ko);
      pa1 = *reinterpret_cast<const float4*>(Abase + (size_t)r1 * Iz + ko);
      pb0 = *reinterpret_cast<const float4*>(Bbase + (size_t)r0 * Iz + ko);
      pb1 = *reinterpret_cast<const float4*>(Bbase + (size_t)r1 * Iz + ko);
    }

#pragma unroll
    for (int ks = 0; ks < 2; ++ks) {
      const int k0 = ks * 8;
      uint32_t ah[4][4], al[4][4];
#pragma unroll
      for (int mt = 0; mt < 4; ++mt) {
        const int ra = wm * 64 + mt * 16 + gid;
        ah[mt][0] = Ah[ra][k0 + tig];
        ah[mt][1] = Ah[ra + 8][k0 + tig];
        ah[mt][2] = Ah[ra][k0 + tig + 4];
        ah[mt][3] = Ah[ra + 8][k0 + tig + 4];
        al[mt][0] = Al[ra][k0 + tig];
        al[mt][1] = Al[ra + 8][k0 + tig];
        al[mt][2] = Al[ra][k0 + tig + 4];
        al[mt][3] = Al[ra + 8][k0 + tig + 4];
      }
      uint32_t bh[4][2], bl[4][2];
#pragma unroll
      for (int nt = 0; nt < 4; ++nt) {
        const int rb = wn * 32 + nt * 8 + gid;
        bh[nt][0] = Bh[rb][k0 + tig];
        bh[nt][1] = Bh[rb][k0 + tig + 4];
        bl[nt][0] = Bl[rb][k0 + tig];
        bl[nt][1] = Bl[rb][k0 + tig + 4];
      }
#pragma unroll
      for (int mt = 0; mt < 4; ++mt)
#pragma unroll
        for (int nt = 0; nt < 4; ++nt) {
          mma_tf32(c[mt][nt], ah[mt][0], ah[mt][1], ah[mt][2], ah[mt][3],
                   bl[nt][0], bl[nt][1]);
          mma_tf32(c[mt][nt], al[mt][0], al[mt][1], al[mt][2], al[mt][3],
                   bh[nt][0], bh[nt][1]);
          mma_tf32(c[mt][nt], ah[mt][0], ah[mt][1], ah[mt][2], ah[mt][3],
                   bh[nt][0], bh[nt][1]);
        }
    }
    __syncthreads();
  }

#pragma unroll
  for (int nt = 0; nt < 4; ++nt) {
    const int n = bn * 128 + wn * 32 + nt * 8 + 2 * tig;
    const float bx = bih[n] + bhh[n];
    const float by = bih[n + 1] + bhh[n + 1];
#pragma unroll
    for (int mt = 0; mt < 4; ++mt) {
      const int m = bm * 128 + wm * 64 + mt * 16 + gid;
      float2 v0 = make_float2(c[mt][nt][0] + bx, c[mt][nt][1] + by);
      float2 v1 = make_float2(c[mt][nt][2] + bx, c[mt][nt][3] + by);
      *reinterpret_cast<float2*>(&g_pre[(size_t)m * Hz + n]) = v0;
      *reinterpret_cast<float2*>(&g_pre[(size_t)(m + 8) * Hz + n]) = v1;
    }
  }
}

// ---------------------------------------------------------------------------
// grid barrier (R3-proven)
// ---------------------------------------------------------------------------
__device__ __forceinline__ void grid_barrier() {
  __syncthreads();
  if (threadIdx.x == 0) {
    unsigned gen = *(volatile unsigned*)&g_gen;
    __threadfence();
    if (atomicAdd(&g_cnt, 1) == NBLK - 1) {
      g_cnt = 0;
      __threadfence();
      atomicAdd(&g_gen, 1);
    } else {
      while (*(volatile unsigned*)&g_gen == gen) __nanosleep(32);
    }
    __threadfence();
  }
  __syncthreads();
}

// ---------------------------------------------------------------------------
// Phase 2: persistent mma.sync tf32 kernel.
// 128 blocks x 256 thr. Block tile 32(M) x 64(N); grid = 8 mtiles x 16 ntiles.
// BK=64 chunks (16/group). Warps 2(m) x 4(n); warp tile 16m x 16n
// (1 mtile x 2 ntiles of m16n8k8), 3-pass tf32 split, fp32 accum.
// ---------------------------------------------------------------------------
__global__ __launch_bounds__(256, 1) void rnn_persistent_mma(
    const float* __restrict__ hs, const float* __restrict__ Whh,
    float* __restrict__ out, float* __restrict__ hf) {
  __shared__ uint32_t Ah[32][68], Al[32][68];
  __shared__ uint32_t Bh[64][68], Bl[64][68];

  const int tid = threadIdx.x;
  const int bmi = blockIdx.x >> 4;  // 0..7  over M=256
  const int bni = blockIdx.x & 15;  // 0..15 over N=1024

  const int w = tid >> 5;
  const int lane = tid & 31;
  const int gid = lane >> 2;  // 0..7
  const int tig = lane & 3;   // 0..3
  const int wm = w >> 2;      // 0..1
  const int wn = w & 3;       // 0..3

  // A loader: tile row arow (0..31), k-quad pair akq (0..7 -> quads akq, akq+8)
  const int arow = tid >> 3;
  const int akq = tid & 7;
  const int m_abs_l = bmi * 32 + arow;  // 0..255
  const int dl = m_abs_l >> 6;
  const int bl = m_abs_l & 63;
  // B loader: tile row brow (0..63), base quad bkq (0..3 -> quads bkq+4j)
  const int brow = tid >> 2;
  const int bkq = tid & 3;
  const float* Brow = Whh + (size_t)(bni * 64 + brow) * Hz;

  for (int g = 0; g < NGROUP; ++g) {
    const float* Arow =
        (g == 0) ? hs + (size_t)m_abs_l * Hz
                 : out + ((size_t)bl * Sz + (4 * g + dl - 4)) * Hz;

    float c[2][4];
#pragma unroll
    for (int nt = 0; nt < 2; ++nt)
#pragma unroll
      for (int e = 0; e < 4; ++e) c[nt][e] = 0.f;

    // prefetch chunk 0
    float4 pa[2], pb[4];
    pa[0] = *reinterpret_cast<const float4*>(Arow + akq * 4);
    pa[1] = *reinterpret_cast<const float4*>(Arow + (akq + 8) * 4);
#pragma unroll
    for (int j = 0; j < 4; ++j)
      pb[j] = *reinterpret_cast<const float4*>(Brow + (bkq + 4 * j) * 4);

    const int NCH = Hz / 64;  // 16
    for (int ch = 0; ch < NCH; ++ch) {
      {
        uint4 h, l;
        split4(pa[0], h, l);
        *reinterpret_cast<uint4*>(&Ah[arow][akq * 4]) = h;
        *reinterpret_cast<uint4*>(&Al[arow][akq * 4]) = l;
        split4(pa[1], h, l);
        *reinterpret_cast<uint4*>(&Ah[arow][(akq + 8) * 4]) = h;
        *reinterpret_cast<uint4*>(&Al[arow][(akq + 8) * 4]) = l;
#pragma unroll
        for (int j = 0; j < 4; ++j) {
          split4(pb[j], h, l);
          *reinterpret_cast<uint4*>(&Bh[brow][(bkq + 4 * j) * 4]) = h;
          *reinterpret_cast<uint4*>(&Bl[brow][(bkq + 4 * j) * 4]) = l;
        }
      }
      __syncthreads();

      if (ch + 1 < NCH) {
        const int ko = (ch + 1) * 64;
        pa[0] = *reinterpret_cast<const float4*>(Arow + ko + akq * 4);
        pa[1] = *reinterpret_cast<const float4*>(Arow + ko + (akq + 8) * 4);
#pragma unroll
        for (int j = 0; j < 4; ++j)
          pb[j] =
              *reinterpret_cast<const float4*>(Brow + ko + (bkq + 4 * j) * 4);
      }

#pragma unroll
      for (int ks = 0; ks < 8; ++ks) {
        const int k0 = ks * 8;
        const int ra = wm * 16 + gid;
        uint32_t ah0 = Ah[ra][k0 + tig];
        uint32_t ah1 = Ah[ra + 8][k0 + tig];
        uint32_t ah2 = Ah[ra][k0 + tig + 4];
        uint32_t ah3 = Ah[ra + 8][k0 + tig + 4];
        uint32_t al0 = Al[ra][k0 + tig];
        uint32_t al1 = Al[ra + 8][k0 + tig];
        uint32_t al2 = Al[ra][k0 + tig + 4];
        uint32_t al3 = Al[ra + 8][k0 + tig + 4];
#pragma unroll
        for (int nt = 0; nt < 2; ++nt) {
          const int rb = wn * 16 + nt * 8 + gid;
          uint32_t bh0 = Bh[rb][k0 + tig];
          uint32_t bh1 = Bh[rb][k0 + tig + 4];
          uint32_t bl0 = Bl[rb][k0 + tig];
          uint32_t bl1 = Bl[rb][k0 + tig + 4];
          mma_tf32(c[nt], ah0, ah1, ah2, ah3, bl0, bl1);
          mma_tf32(c[nt], al0, al1, al2, al3, bh0, bh1);
          mma_tf32(c[nt], ah0, ah1, ah2, ah3, bh0, bh1);
        }
      }
      __syncthreads();
    }

    // epilogue: tanh(pre + acc) -> out (+ h_final on last group)
#pragma unroll
    for (int nt = 0; nt < 2; ++nt) {
      const int n = bni * 64 + wn * 16 + nt * 8 + 2 * tig;
#pragma unroll
      for (int half = 0; half < 2; ++half) {
        const int m_abs = bmi * 32 + wm * 16 + gid + half * 8;
        const int d = m_abs >> 6;
        const int b = m_abs & 63;
        const size_t base = ((size_t)b * Sz + (4 * g + d)) * Hz + n;
        float2 pv = *reinterpret_cast<const float2*>(&g_pre[base]);
        float2 ov = make_float2(tanhf(pv.x + c[nt][half * 2 + 0]),
                                tanhf(pv.y + c[nt][half * 2 + 1]));
        *reinterpret_cast<float2*>(&out[base]) = ov;
        if (g == NGROUP - 1) {
          *reinterpret_cast<float2*>(&hf[((size_t)d * Bz + b) * Hz + n]) = ov;
        }
      }
    }
    grid_barrier();
  }
}

extern "C" void kernel_launch(void* const* d_in, const int* in_sizes, int n_in,
                              void* d_out, int out_size) {
  (void)in_sizes;
  (void)n_in;
  (void)out_size;
  const float* X = (const float*)d_in[0];    // [B,S,I]
  const float* hs = (const float*)d_in[1];   // [4,B,H]
  const float* Wih = (const float*)d_in[2];  // [H,I]
  const float* Whh = (const float*)d_in[3];  // [H,H]
  const float* bih = (const float*)d_in[4];  // [H]
  const float* bhh = (const float*)d_in[5];  // [H]

  float* out = (float*)d_out;              // [B,S,H]
  float* hf = out + (size_t)Bz * Sz * Hz;  // [4,B,H]

  pre_gemm_mma<<<dim3(Hz / 128, (Bz * Sz) / 128), 256>>>(X, Wih, bih, bhh);

  rnn_persistent_mma<<<NBLK, 256>>>(hs, Whh, out, hf);
}

// round 11
// speedup vs baseline: 1.6940x; 1.0162x over previous
#include <cuda_runtime.h>
#include <math.h>
#include <cstdint>

// RNNLayer_73074573574765: delayed RNN. B=64,S=512,I=H=1024,DELAY=4.
// Phase 1: pre = X.Wih^T + bih + bhh  -- mma.sync tf32 3-pass, ldmatrix frags
// Phase 2: persistent mma.sync tf32 3-pass kernel, ldmatrix frags;
//          128 groups, grid barrier; last group also writes h_final.

namespace {
constexpr int Bz = 64;
constexpr int Sz = 512;
constexpr int Iz = 1024;
constexpr int Hz = 1024;
constexpr int DZ = 4;
constexpr int NBLK = 128;
constexpr int NGROUP = Sz / DZ;  // 128
}  // namespace

__device__ float g_pre[(size_t)Bz * Sz * Hz];
__device__ unsigned g_cnt;  // zero-init; self-cleaning
__device__ unsigned g_gen;  // monotonic; equality-compared (replay-safe)

// ---------------- PTX helpers (base-target legal) ----------------
__device__ __forceinline__ uint32_t cvt_tf32(float f) {
  uint32_t r;
  asm("cvt.rna.tf32.f32 %0, %1;" : "=r"(r) : "f"(f));
  return r;
}
__device__ __forceinline__ void mma_tf32(float* c, uint32_t a0, uint32_t a1,
                                         uint32_t a2, uint32_t a3, uint32_t b0,
                                         uint32_t b1) {
  asm volatile(
      "mma.sync.aligned.m16n8k8.row.col.f32.tf32.tf32.f32 "
      "{%0,%1,%2,%3}, {%4,%5,%6,%7}, {%8,%9}, {%0,%1,%2,%3};"
      : "+f"(c[0]), "+f"(c[1]), "+f"(c[2]), "+f"(c[3])
      : "r"(a0), "r"(a1), "r"(a2), "r"(a3), "r"(b0), "r"(b1));
}
__device__ __forceinline__ void split_tf32(float x, uint32_t& hi,
                                           uint32_t& lo) {
  hi = cvt_tf32(x);
  lo = cvt_tf32(x - __uint_as_float(hi));
}
__device__ __forceinline__ void split4(float4 v, uint4& h, uint4& l) {
  split_tf32(v.x, h.x, l.x);
  split_tf32(v.y, h.y, l.y);
  split_tf32(v.z, h.z, l.z);
  split_tf32(v.w, h.w, l.w);
}
__device__ __forceinline__ uint32_t smem_u32(const void* p) {
  uint32_t a;
  asm("{ .reg .u64 t; cvta.to.shared.u64 t, %1; cvt.u32.u64 %0, t; }"
      : "=r"(a) : "l"(p));
  return a;
}
// ldmatrix x4 of four 8x(16B) tiles; for tf32 frags (4B "columns").
__device__ __forceinline__ void ldsm4(uint32_t& r0, uint32_t& r1, uint32_t& r2,
                                      uint32_t& r3, uint32_t addr) {
  asm volatile(
      "ldmatrix.sync.aligned.m8n8.x4.shared.b16 {%0,%1,%2,%3}, [%4];"
      : "=r"(r0), "=r"(r1), "=r"(r2), "=r"(r3)
      : "r"(addr));
}

// ---------------------------------------------------------------------------
// Phase 1: pre[m,n] = sum_k X[m,k]*Wih[n,k] + bih[n]+bhh[n]
// 128x128 block tile, BK=16, 256 thr (warps 2m x 4n), warp tile 64x32.
// 3xTF32 split; fragments via ldmatrix.
// ---------------------------------------------------------------------------
__global__ __launch_bounds__(256) void pre_gemm_mma(
    const float* __restrict__ X, const float* __restrict__ Wih,
    const float* __restrict__ bih, const float* __restrict__ bhh) {
  __shared__ __align__(16) uint32_t Ah[128][20];
  __shared__ __align__(16) uint32_t Al[128][20];
  __shared__ __align__(16) uint32_t Bh[128][20];
  __shared__ __align__(16) uint32_t Bl[128][20];

  const int tid = threadIdx.x;
  const int bn = blockIdx.x;
  const int bm = blockIdx.y;
  const int w = tid >> 5;
  const int lane = tid & 31;
  const int gid = lane >> 2;
  const int tig = lane & 3;
  const int wm = w >> 2;
  const int wn = w & 3;

  const int r0 = tid >> 2;
  const int r1 = r0 + 64;
  const int q = tid & 3;
  const float* Abase = X + (size_t)(bm * 128) * Iz;
  const float* Bbase = Wih + (size_t)(bn * 128) * Iz;

  // ldmatrix lane addressing: lanes 0-15 -> rows, lanes 16-31 -> rows @ k+4
  const int rowL = lane & 15;
  const int kL = (lane >> 4) * 4;
  const uint32_t aS = smem_u32(Ah), alS = smem_u32(Al);
  const uint32_t bS = smem_u32(Bh), blS = smem_u32(Bl);
  const uint32_t aoff = ((uint32_t)((wm * 64 + rowL) * 20 + kL)) * 4;
  const uint32_t boff = ((uint32_t)((wn * 32 + rowL) * 20 + kL)) * 4;

  float c[4][4][4];
#pragma unroll
  for (int i = 0; i < 4; i++)
#pragma unroll
    for (int j = 0; j < 4; j++)
#pragma unroll
      for (int e = 0; e < 4; e++) c[i][j][e] = 0.f;

  float4 pa0, pa1, pb0, pb1;
  pa0 = *reinterpret_cast<const float4*>(Abase + (size_t)r0 * Iz + q * 4);
  pa1 = *reinterpret_cast<const float4*>(Abase + (size_t)r1 * Iz + q * 4);
  pb0 = *reinterpret_cast<const float4*>(Bbase + (size_t)r0 * Iz + q * 4);
  pb1 = *reinterpret_cast<const float4*>(Bbase + (size_t)r1 * Iz + q * 4);

  const int NCH = Iz / 16;  // 64
  for (int ch = 0; ch < NCH; ++ch) {
    {
      uint4 h, l;
      split4(pa0, h, l);
      *reinterpret_cast<uint4*>(&Ah[r0][q * 4]) = h;
      *reinterpret_cast<uint4*>(&Al[r0][q * 4]) = l;
      split4(pa1, h, l);
      *reinterpret_cast<uint4*>(&Ah[r1][q * 4]) = h;
      *reinterpret_cast<uint4*>(&Al[r1][q * 4]) = l;
      split4(pb0, h, l);
      *reinterpret_cast<uint4*>(&Bh[r0][q * 4]) = h;
      *reinterpret_cast<uint4*>(&Bl[r0][q * 4]) = l;
      split4(pb1, h, l);
      *reinterpret_cast<uint4*>(&Bh[r1][q * 4]) = h;
      *reinterpret_cast<uint4*>(&Bl[r1][q * 4]) = l;
    }
    __syncthreads();

    if (ch + 1 < NCH) {
      const size_t ko = (size_t)(ch + 1) * 16 + q * 4;
      pa0 = *reinterpret_cast<const float4*>(Abase + (size_t)r0 * Iz + ko);
      pa1 = *reinterpret_cast<const float4*>(Abase + (size_t)r1 * Iz + ko);
      pb0 = *reinterpret_cast<const float4*>(Bbase + (size_t)r0 * Iz + ko);
      pb1 = *reinterpret_cast<const float4*>(Bbase + (size_t)r1 * Iz + ko);
    }

#pragma unroll
    for (int ks = 0; ks < 2; ++ks) {
      const uint32_t kb = ks * 32;  // 8 floats = 32B
      uint32_t ah[4][4], al[4][4];
#pragma unroll
      for (int mt = 0; mt < 4; ++mt) {
        ldsm4(ah[mt][0], ah[mt][1], ah[mt][2], ah[mt][3],
              aS + aoff + mt * (16 * 20 * 4) + kb);
        ldsm4(al[mt][0], al[mt][1], al[mt][2], al[mt][3],
              alS + aoff + mt * (16 * 20 * 4) + kb);
      }
      // pairs of ntiles: x4 covers 16 n-rows -> regs {b0_e, b0_o, b1_e, b1_o}
      uint32_t bh[2][4], bl[2][4];
#pragma unroll
      for (int p = 0; p < 2; ++p) {
        ldsm4(bh[p][0], bh[p][1], bh[p][2], bh[p][3],
              bS + boff + p * (16 * 20 * 4) + kb);
        ldsm4(bl[p][0], bl[p][1], bl[p][2], bl[p][3],
              blS + boff + p * (16 * 20 * 4) + kb);
      }
#pragma unroll
      for (int mt = 0; mt < 4; ++mt)
#pragma unroll
        for (int nt = 0; nt < 4; ++nt) {
          const int p = nt >> 1, o = nt & 1;
          mma_tf32(c[mt][nt], ah[mt][0], ah[mt][1], ah[mt][2], ah[mt][3],
                   bl[p][o], bl[p][o + 2]);
          mma_tf32(c[mt][nt], al[mt][0], al[mt][1], al[mt][2], al[mt][3],
                   bh[p][o], bh[p][o + 2]);
          mma_tf32(c[mt][nt], ah[mt][0], ah[mt][1], ah[mt][2], ah[mt][3],
                   bh[p][o], bh[p][o + 2]);
        }
    }
    __syncthreads();
  }

#pragma unroll
  for (int nt = 0; nt < 4; ++nt) {
    const int n = bn * 128 + wn * 32 + nt * 8 + 2 * tig;
    const float bx = bih[n] + bhh[n];
    const float by = bih[n + 1] + bhh[n + 1];
#pragma unroll
    for (int mt = 0; mt < 4; ++mt) {
      const int m = bm * 128 + wm * 64 + mt * 16 + gid;
      float2 v0 = make_float2(c[mt][nt][0] + bx, c[mt][nt][1] + by);
      float2 v1 = make_float2(c[mt][nt][2] + bx, c[mt][nt][3] + by);
      *reinterpret_cast<float2*>(&g_pre[(size_t)m * Hz + n]) = v0;
      *reinterpret_cast<float2*>(&g_pre[(size_t)(m + 8) * Hz + n]) = v1;
    }
  }
}

// ---------------------------------------------------------------------------
// grid barrier (R3-proven)
// ---------------------------------------------------------------------------
__device__ __forceinline__ void grid_barrier() {
  __syncthreads();
  if (threadIdx.x == 0) {
    unsigned gen = *(volatile unsigned*)&g_gen;
    __threadfence();
    if (atomicAdd(&g_cnt, 1) == NBLK - 1) {
      g_cnt = 0;
      __threadfence();
      atomicAdd(&g_gen, 1);
    } else {
      while (*(volatile unsigned*)&g_gen == gen) __nanosleep(32);
    }
    __threadfence();
  }
  __syncthreads();
}

// ---------------------------------------------------------------------------
// Phase 2: persistent mma.sync tf32 kernel, ldmatrix frags.
// 128 blocks x 256 thr. Block tile 32m x 64n (grid 8 x 16). BK=64 (16/group).
// Warps 2m x 4n; warp tile 16m x 16n; 3-pass split.
// ---------------------------------------------------------------------------
__global__ __launch_bounds__(256, 1) void rnn_persistent_mma(
    const float* __restrict__ hs, const float* __restrict__ Whh,
    float* __restrict__ out, float* __restrict__ hf) {
  __shared__ __align__(16) uint32_t Ah[32][68], Al[32][68];
  __shared__ __align__(16) uint32_t Bh[64][68], Bl[64][68];

  const int tid = threadIdx.x;
  const int bmi = blockIdx.x >> 4;  // 0..7  over M=256
  const int bni = blockIdx.x & 15;  // 0..15 over N=1024

  const int w = tid >> 5;
  const int lane = tid & 31;
  const int gid = lane >> 2;
  const int tig = lane & 3;
  const int wm = w >> 2;  // 0..1
  const int wn = w & 3;   // 0..3

  // A loader: tile row arow (0..31), k-quad pair akq
  const int arow = tid >> 3;
  const int akq = tid & 7;
  const int m_abs_l = bmi * 32 + arow;
  const int dl = m_abs_l >> 6;
  const int bl_ = m_abs_l & 63;
  // B loader
  const int brow = tid >> 2;
  const int bkq = tid & 3;
  const float* Brow = Whh + (size_t)(bni * 64 + brow) * Hz;

  // ldmatrix lane addressing
  const int rowL = lane & 15;
  const int kL = (lane >> 4) * 4;
  const uint32_t aHS = smem_u32(Ah) + ((uint32_t)((wm * 16 + rowL) * 68 + kL)) * 4;
  const uint32_t aLS = smem_u32(Al) + ((uint32_t)((wm * 16 + rowL) * 68 + kL)) * 4;
  const uint32_t bHS = smem_u32(Bh) + ((uint32_t)((wn * 16 + rowL) * 68 + kL)) * 4;
  const uint32_t bLS = smem_u32(Bl) + ((uint32_t)((wn * 16 + rowL) * 68 + kL)) * 4;

  for (int g = 0; g < NGROUP; ++g) {
    const float* Arow =
        (g == 0) ? hs + (size_t)m_abs_l * Hz
                 : out + ((size_t)bl_ * Sz + (4 * g + dl - 4)) * Hz;

    float c[2][4];
#pragma unroll
    for (int nt = 0; nt < 2; ++nt)
#pragma unroll
      for (int e = 0; e < 4; ++e) c[nt][e] = 0.f;

    float4 pa[2], pb[4];
    pa[0] = *reinterpret_cast<const float4*>(Arow + akq * 4);
    pa[1] = *reinterpret_cast<const float4*>(Arow + (akq + 8) * 4);
#pragma unroll
    for (int j = 0; j < 4; ++j)
      pb[j] = *reinterpret_cast<const float4*>(Brow + (bkq + 4 * j) * 4);

    const int NCH = Hz / 64;  // 16
    for (int ch = 0; ch < NCH; ++ch) {
      {
        uint4 h, l;
        split4(pa[0], h, l);
        *reinterpret_cast<uint4*>(&Ah[arow][akq * 4]) = h;
        *reinterpret_cast<uint4*>(&Al[arow][akq * 4]) = l;
        split4(pa[1], h, l);
        *reinterpret_cast<uint4*>(&Ah[arow][(akq + 8) * 4]) = h;
        *reinterpret_cast<uint4*>(&Al[arow][(akq + 8) * 4]) = l;
#pragma unroll
        for (int j = 0; j < 4; ++j) {
          split4(pb[j], h, l);
          *reinterpret_cast<uint4*>(&Bh[brow][(bkq + 4 * j) * 4]) = h;
          *reinterpret_cast<uint4*>(&Bl[brow][(bkq + 4 * j) * 4]) = l;
        }
      }
      __syncthreads();

      if (ch + 1 < NCH) {
        const int ko = (ch + 1) * 64;
        pa[0] = *reinterpret_cast<const float4*>(Arow + ko + akq * 4);
        pa[1] = *reinterpret_cast<const float4*>(Arow + ko + (akq + 8) * 4);
#pragma unroll
        for (int j = 0; j < 4; ++j)
          pb[j] =
              *reinterpret_cast<const float4*>(Brow + ko + (bkq + 4 * j) * 4);
      }

#pragma unroll
      for (int ks = 0; ks < 8; ++ks) {
        const uint32_t kb = ks * 32;  // 8 floats = 32B
        uint32_t ah0, ah1, ah2, ah3, al0, al1, al2, al3;
        ldsm4(ah0, ah1, ah2, ah3, aHS + kb);
        ldsm4(al0, al1, al2, al3, aLS + kb);
        // B x4 over 16 n-rows: regs {b0_nt0, b0_nt1, b1_nt0, b1_nt1}
        uint32_t bh0, bh1, bh2, bh3, bl0, bl1, bl2, bl3;
        ldsm4(bh0, bh1, bh2, bh3, bHS + kb);
        ldsm4(bl0, bl1, bl2, bl3, bLS + kb);

        mma_tf32(c[0], ah0, ah1, ah2, ah3, bl0, bl2);
        mma_tf32(c[0], al0, al1, al2, al3, bh0, bh2);
        mma_tf32(c[0], ah0, ah1, ah2, ah3, bh0, bh2);
        mma_tf32(c[1], ah0, ah1, ah2, ah3, bl1, bl3);
        mma_tf32(c[1], al0, al1, al2, al3, bh1, bh3);
        mma_tf32(c[1], ah0, ah1, ah2, ah3, bh1, bh3);
      }
      __syncthreads();
    }

    // epilogue: tanh(pre + acc) -> out (+ h_final on last group)
#pragma unroll
    for (int nt = 0; nt < 2; ++nt) {
      const int n = bni * 64 + wn * 16 + nt * 8 + 2 * tig;
#pragma unroll
      for (int half = 0; half < 2; ++half) {
        const int m_abs = bmi * 32 + wm * 16 + gid + half * 8;
        const int d = m_abs >> 6;
        const int b = m_abs & 63;
        const size_t base = ((size_t)b * Sz + (4 * g + d)) * Hz + n;
        float2 pv = *reinterpret_cast<const float2*>(&g_pre[base]);
        float2 ov = make_float2(tanhf(pv.x + c[nt][half * 2 + 0]),
                                tanhf(pv.y + c[nt][half * 2 + 1]));
        *reinterpret_cast<float2*>(&out[base]) = ov;
        if (g == NGROUP - 1) {
          *reinterpret_cast<float2*>(&hf[((size_t)d * Bz + b) * Hz + n]) = ov;
        }
      }
    }
    grid_barrier();
  }
}

extern "C" void kernel_launch(void* const* d_in, const int* in_sizes, int n_in,
                              void* d_out, int out_size) {
  (void)in_sizes;
  (void)n_in;
  (void)out_size;
  const float* X = (const float*)d_in[0];    // [B,S,I]
  const float* hs = (const float*)d_in[1];   // [4,B,H]
  const float* Wih = (const float*)d_in[2];  // [H,I]
  const float* Whh = (const float*)d_in[3];  // [H,H]
  const float* bih = (const float*)d_in[4];  // [H]
  const float* bhh = (const float*)d_in[5];  // [H]

  float* out = (float*)d_out;              // [B,S,H]
  float* hf = out + (size_t)Bz * Sz * Hz;  // [4,B,H]

  pre_gemm_mma<<<dim3(Hz / 128, (Bz * Sz) / 128), 256>>>(X, Wih, bih, bhh);

  rnn_persistent_mma<<<NBLK, 256>>>(hs, Whh, out, hf);
}